// round 1
// baseline (speedup 1.0000x reference)
#include <cuda_runtime.h>
#include <math.h>

#define NB 4
#define NC 256
#define NN 4096

#define SQ 260     // padded row stride (floats) for Q/K/V smem tiles: 1040B % 128 = 16
#define SSTR 68    // S/P tile row stride (floats)

// scratch: q/k/v stored transposed as (B, N, C)
__device__ float g_q[NB*NN*NC];
__device__ float g_k[NB*NN*NC];
__device__ float g_v[NB*NN*NC];

__device__ __forceinline__ void fma4(float4& a, float s, const float4& v) {
    a.x += s * v.x; a.y += s * v.y; a.z += s * v.z; a.w += s * v.w;
}
__device__ __forceinline__ float dot4(const float4& a, const float4& b) {
    return a.x*b.x + a.y*b.y + a.z*b.z + a.w*b.w;
}

// ---------------------------------------------------------------------------
// QKV projection: dst[b][n][c] = sum_cc W[c][cc] * x[b][cc][n]
// grid (NN/64, NC/64, 3*NB), 256 threads, 64x64 tile, 4x4 micro-tile
// ---------------------------------------------------------------------------
__global__ __launch_bounds__(256, 4)
void qkv_proj_kernel(const float* __restrict__ x,
                     const float* __restrict__ Wq,
                     const float* __restrict__ Wk,
                     const float* __restrict__ Wv)
{
    __shared__ float Xs[16][68];
    __shared__ float Ws[16][68];

    const int b = blockIdx.z / 3;
    const int w = blockIdx.z % 3;
    const float* __restrict__ Wm = (w == 0) ? Wq : (w == 1) ? Wk : Wv;
    float* __restrict__ dst      = (w == 0) ? g_q : (w == 1) ? g_k : g_v;

    const int n0 = blockIdx.x * 64;
    const int c0 = blockIdx.y * 64;
    const int t  = threadIdx.x;
    const int ty = t >> 4, tx = t & 15;

    float4 acc[4];
    #pragma unroll
    for (int i = 0; i < 4; i++) acc[i] = make_float4(0.f, 0.f, 0.f, 0.f);

    const int xr = t >> 4, xn = t & 15;   // X loader: (cc row, n quad)
    const int wc = t >> 2, wq = t & 3;    // W loader: (c row, cc quad)

    for (int cc0 = 0; cc0 < NC; cc0 += 16) {
        *(float4*)&Xs[xr][xn * 4] =
            *(const float4*)&x[(b*NC + cc0 + xr)*NN + n0 + xn*4];
        float4 wv = *(const float4*)&Wm[(c0 + wc)*NC + cc0 + wq*4];
        Ws[wq*4 + 0][wc] = wv.x;
        Ws[wq*4 + 1][wc] = wv.y;
        Ws[wq*4 + 2][wc] = wv.z;
        Ws[wq*4 + 3][wc] = wv.w;
        __syncthreads();

        #pragma unroll
        for (int cc = 0; cc < 16; cc++) {
            float4 xv  = *(float4*)&Xs[cc][ty * 4];
            float4 wvv = *(float4*)&Ws[cc][tx * 4];
            fma4(acc[0], xv.x, wvv);
            fma4(acc[1], xv.y, wvv);
            fma4(acc[2], xv.z, wvv);
            fma4(acc[3], xv.w, wvv);
        }
        __syncthreads();
    }

    #pragma unroll
    for (int i = 0; i < 4; i++)
        *(float4*)&dst[(b*NN + n0 + ty*4 + i)*NC + c0 + tx*4] = acc[i];
}

// ---------------------------------------------------------------------------
// Fused flash attention + residual epilogue.
// grid (NN/64, NB), 256 threads. BM=64 queries, BN=64 keys/iter, d=256.
// Thread (ty,tx): S micro 4x4 (rows ty*4+i, cols tx+16j);
//                 O acc rows ty*4+i, col-quads tx+16k (4 rows x 16 cols).
// ---------------------------------------------------------------------------
__global__ __launch_bounds__(256, 1)
void flash_kernel(const float* __restrict__ x,
                  const float* __restrict__ gamma,
                  float* __restrict__ out)
{
    extern __shared__ float sm[];
    float* Qs     = sm;                 // 64*SQ
    float* Ks     = Qs + 64*SQ;         // 64*SQ
    float* Vs     = Ks + 64*SQ;         // 64*SQ
    float* Ss     = Vs + 64*SQ;         // 64*SSTR
    float* m_row  = Ss + 64*SSTR;       // 64
    float* l_row  = m_row + 64;         // 64
    float* s_scal = l_row + 64;         // 64

    const int b  = blockIdx.y;
    const int n0 = blockIdx.x * 64;
    const int t  = threadIdx.x;
    const int ty = t >> 4, tx = t & 15;

    // load Q tile (64 x 256)
    for (int i = t; i < 64*64; i += 256) {
        int r = i >> 6, c4 = i & 63;
        *(float4*)(Qs + r*SQ + c4*4) =
            *(const float4*)(g_q + (b*NN + n0 + r)*NC + c4*4);
    }
    if (t < 64) { m_row[t] = -INFINITY; l_row[t] = 0.f; }

    float4 accv[4][4];
    #pragma unroll
    for (int i = 0; i < 4; i++)
        #pragma unroll
        for (int k = 0; k < 4; k++) accv[i][k] = make_float4(0.f, 0.f, 0.f, 0.f);

    for (int kt = 0; kt < 64; kt++) {
        const int k0 = kt * 64;
        // load K,V tiles
        for (int i = t; i < 64*64; i += 256) {
            int r = i >> 6, c4 = i & 63;
            *(float4*)(Ks + r*SQ + c4*4) =
                *(const float4*)(g_k + (b*NN + k0 + r)*NC + c4*4);
            *(float4*)(Vs + r*SQ + c4*4) =
                *(const float4*)(g_v + (b*NN + k0 + r)*NC + c4*4);
        }
        __syncthreads();

        // --- S = Q K^T (64x64 tile) ---
        float sacc[4][4];
        #pragma unroll
        for (int i = 0; i < 4; i++)
            #pragma unroll
            for (int j = 0; j < 4; j++) sacc[i][j] = 0.f;

        #pragma unroll 4
        for (int c4 = 0; c4 < 64; c4++) {
            float4 qv[4], kv[4];
            #pragma unroll
            for (int i = 0; i < 4; i++)
                qv[i] = *(float4*)(Qs + (ty*4 + i)*SQ + c4*4);
            #pragma unroll
            for (int j = 0; j < 4; j++)
                kv[j] = *(float4*)(Ks + (tx + 16*j)*SQ + c4*4);
            #pragma unroll
            for (int i = 0; i < 4; i++)
                #pragma unroll
                for (int j = 0; j < 4; j++)
                    sacc[i][j] += dot4(qv[i], kv[j]);
        }
        #pragma unroll
        for (int i = 0; i < 4; i++)
            #pragma unroll
            for (int j = 0; j < 4; j++)
                Ss[(ty*4 + i)*SSTR + tx + 16*j] = sacc[i][j];
        __syncthreads();

        // --- online softmax: 4 lanes per row ---
        {
            const int r = t >> 2, q = t & 3;
            float* srow = Ss + r*SSTR + q*16;
            float mx = -INFINITY;
            #pragma unroll
            for (int k = 0; k < 16; k++) mx = fmaxf(mx, srow[k]);
            mx = fmaxf(mx, __shfl_xor_sync(0xffffffffu, mx, 1));
            mx = fmaxf(mx, __shfl_xor_sync(0xffffffffu, mx, 2));
            const float m_old = m_row[r];
            const float m_new = fmaxf(m_old, mx);
            float ps = 0.f;
            #pragma unroll
            for (int k = 0; k < 16; k++) {
                float p = __expf(srow[k] - m_new);
                srow[k] = p;
                ps += p;
            }
            ps += __shfl_xor_sync(0xffffffffu, ps, 1);
            ps += __shfl_xor_sync(0xffffffffu, ps, 2);
            if (q == 0) {
                float corr = __expf(m_old - m_new);   // 0 on first tile
                s_scal[r] = corr;
                l_row[r]  = l_row[r]*corr + ps;
                m_row[r]  = m_new;
            }
        }
        __syncthreads();

        // --- O = O*corr + P V ---
        {
            float sc[4];
            #pragma unroll
            for (int i = 0; i < 4; i++) sc[i] = s_scal[ty*4 + i];
            #pragma unroll
            for (int i = 0; i < 4; i++)
                #pragma unroll
                for (int k = 0; k < 4; k++) {
                    accv[i][k].x *= sc[i]; accv[i][k].y *= sc[i];
                    accv[i][k].z *= sc[i]; accv[i][k].w *= sc[i];
                }
            #pragma unroll 4
            for (int m = 0; m < 64; m++) {
                float p[4];
                #pragma unroll
                for (int i = 0; i < 4; i++) p[i] = Ss[(ty*4 + i)*SSTR + m];
                float4 vv[4];
                #pragma unroll
                for (int k = 0; k < 4; k++)
                    vv[k] = *(float4*)(Vs + m*SQ + (tx + 16*k)*4);
                #pragma unroll
                for (int i = 0; i < 4; i++)
                    #pragma unroll
                    for (int k = 0; k < 4; k++)
                        fma4(accv[i][k], p[i], vv[k]);
            }
        }
        __syncthreads();
    }

    // finalize: divide by l
    {
        float li[4];
        #pragma unroll
        for (int i = 0; i < 4; i++) li[i] = 1.f / l_row[ty*4 + i];
        #pragma unroll
        for (int i = 0; i < 4; i++)
            #pragma unroll
            for (int k = 0; k < 4; k++) {
                accv[i][k].x *= li[i]; accv[i][k].y *= li[i];
                accv[i][k].z *= li[i]; accv[i][k].w *= li[i];
            }
    }

    // transpose O through smem (reuse K/V region), then coalesced epilogue
    float* Ot = Ks;  // 256 x SSTR floats = 17408 <= 2*64*SQ
    #pragma unroll
    for (int i = 0; i < 4; i++)
        #pragma unroll
        for (int k = 0; k < 4; k++) {
            int cbase = (tx + 16*k) * 4;
            Ot[(cbase + 0)*SSTR + ty*4 + i] = accv[i][k].x;
            Ot[(cbase + 1)*SSTR + ty*4 + i] = accv[i][k].y;
            Ot[(cbase + 2)*SSTR + ty*4 + i] = accv[i][k].z;
            Ot[(cbase + 3)*SSTR + ty*4 + i] = accv[i][k].w;
        }
    __syncthreads();

    const float g = gamma[0];
    #pragma unroll
    for (int pass = 0; pass < 4; pass++) {
        int c = pass*64 + (t >> 2);
        #pragma unroll
        for (int j = 0; j < 4; j++) {
            int f4 = (t & 3) + j*4;
            float4 o  = *(float4*)(Ot + c*SSTR + f4*4);
            float4 xv = *(const float4*)(x + (b*NC + c)*NN + n0 + f4*4);
            float4 r;
            r.x = g*o.x + xv.x; r.y = g*o.y + xv.y;
            r.z = g*o.z + xv.z; r.w = g*o.w + xv.w;
            *(float4*)(out + (b*NC + c)*NN + n0 + f4*4) = r;
        }
    }
}

// ---------------------------------------------------------------------------

extern "C" void kernel_launch(void* const* d_in, const int* in_sizes, int n_in,
                              void* d_out, int out_size)
{
    const float* x     = (const float*)d_in[0];
    const float* Wq    = (const float*)d_in[1];
    const float* Wk    = (const float*)d_in[2];
    const float* Wv    = (const float*)d_in[3];
    const float* gamma = (const float*)d_in[4];
    float* out = (float*)d_out;

    const int smem_bytes = (3*64*SQ + 64*SSTR + 3*64) * (int)sizeof(float); // 217856
    cudaFuncSetAttribute(flash_kernel,
                         cudaFuncAttributeMaxDynamicSharedMemorySize, smem_bytes);

    dim3 gp(NN/64, NC/64, 3*NB);
    qkv_proj_kernel<<<gp, 256>>>(x, Wq, Wk, Wv);

    dim3 gf(NN/64, NB);
    flash_kernel<<<gf, 256, smem_bytes>>>(x, gamma, out);
}

// round 3
// speedup vs baseline: 2.4027x; 2.4027x over previous
#include <cuda_runtime.h>
#include <math.h>

#define NB 4
#define NC 256
#define NN 4096

#define SQ 260     // Q/K smem row stride (floats): banks 4*gid+tig conflict-free
#define SV 264     // V smem row stride: banks 8*tig+gid conflict-free
#define SSTR 68    // S/P and Ot row stride

// scratch: q/k/v stored transposed as (B, N, C), values pre-rounded to tf32
__device__ float g_q[NB*NN*NC];
__device__ float g_k[NB*NN*NC];
__device__ float g_v[NB*NN*NC];

__device__ __forceinline__ void fma4(float4& a, float s, const float4& v) {
    a.x += s * v.x; a.y += s * v.y; a.z += s * v.z; a.w += s * v.w;
}
__device__ __forceinline__ unsigned tf32r(float x) {
    unsigned u; asm("cvt.rna.tf32.f32 %0, %1;" : "=r"(u) : "f"(x)); return u;
}
__device__ __forceinline__ unsigned fbits(float x) { return __float_as_uint(x); }

__device__ __forceinline__ void mma_tf32(float* c, const unsigned* a,
                                         unsigned b0, unsigned b1) {
    asm volatile(
        "mma.sync.aligned.m16n8k8.row.col.f32.tf32.tf32.f32 "
        "{%0,%1,%2,%3}, {%4,%5,%6,%7}, {%8,%9}, {%0,%1,%2,%3};"
        : "+f"(c[0]), "+f"(c[1]), "+f"(c[2]), "+f"(c[3])
        : "r"(a[0]), "r"(a[1]), "r"(a[2]), "r"(a[3]), "r"(b0), "r"(b1));
}

// ---------------------------------------------------------------------------
// QKV projection: dst[b][n][c] = sum_cc W[c][cc] * x[b][cc][n], tf32-rounded.
// ---------------------------------------------------------------------------
__global__ __launch_bounds__(256, 4)
void qkv_proj_kernel(const float* __restrict__ x,
                     const float* __restrict__ Wq,
                     const float* __restrict__ Wk,
                     const float* __restrict__ Wv)
{
    __shared__ float Xs[16][68];
    __shared__ float Ws[16][68];

    const int b = blockIdx.z / 3;
    const int w = blockIdx.z % 3;
    const float* __restrict__ Wm = (w == 0) ? Wq : (w == 1) ? Wk : Wv;
    float* __restrict__ dst      = (w == 0) ? g_q : (w == 1) ? g_k : g_v;

    const int n0 = blockIdx.x * 64;
    const int c0 = blockIdx.y * 64;
    const int t  = threadIdx.x;
    const int ty = t >> 4, tx = t & 15;

    float4 acc[4];
    #pragma unroll
    for (int i = 0; i < 4; i++) acc[i] = make_float4(0.f, 0.f, 0.f, 0.f);

    const int xr = t >> 4, xn = t & 15;
    const int wc = t >> 2, wq = t & 3;

    for (int cc0 = 0; cc0 < NC; cc0 += 16) {
        *(float4*)&Xs[xr][xn * 4] =
            *(const float4*)&x[(b*NC + cc0 + xr)*NN + n0 + xn*4];
        float4 wv = *(const float4*)&Wm[(c0 + wc)*NC + cc0 + wq*4];
        Ws[wq*4 + 0][wc] = wv.x;
        Ws[wq*4 + 1][wc] = wv.y;
        Ws[wq*4 + 2][wc] = wv.z;
        Ws[wq*4 + 3][wc] = wv.w;
        __syncthreads();

        #pragma unroll
        for (int cc = 0; cc < 16; cc++) {
            float4 xv  = *(float4*)&Xs[cc][ty * 4];
            float4 wvv = *(float4*)&Ws[cc][tx * 4];
            fma4(acc[0], xv.x, wvv);
            fma4(acc[1], xv.y, wvv);
            fma4(acc[2], xv.z, wvv);
            fma4(acc[3], xv.w, wvv);
        }
        __syncthreads();
    }

    #pragma unroll
    for (int i = 0; i < 4; i++) {
        acc[i].x = __uint_as_float(tf32r(acc[i].x));
        acc[i].y = __uint_as_float(tf32r(acc[i].y));
        acc[i].z = __uint_as_float(tf32r(acc[i].z));
        acc[i].w = __uint_as_float(tf32r(acc[i].w));
        *(float4*)&dst[(b*NN + n0 + ty*4 + i)*NC + c0 + tx*4] = acc[i];
    }
}

// ---------------------------------------------------------------------------
// Fused flash attention (tf32 mma.sync) + residual epilogue.
// grid (NN/64, NB), 256 threads (8 warps). BM=64 queries, BN=64 keys, d=256.
// S: warp grid 4(row)x2(col), each warp 16x32 of S via m16n8k8.
// PV: computes O^T (d-major); warp w owns d-rows [32w, 32w+32), all 64 queries.
// ---------------------------------------------------------------------------
__global__ __launch_bounds__(256, 1)
void flash_kernel(const float* __restrict__ x,
                  const float* __restrict__ gamma,
                  float* __restrict__ out)
{
    extern __shared__ float sm[];
    float* Qs     = sm;                 // 64*SQ
    float* Ks     = Qs + 64*SQ;         // 64*SQ
    float* Vs     = Ks + 64*SQ;         // 64*SV
    float* Ss     = Vs + 64*SV;         // 64*SSTR
    float* m_row  = Ss + 64*SSTR;       // 64
    float* l_row  = m_row + 64;         // 64
    float* s_scal = l_row + 64;         // 64

    const int b    = blockIdx.y;
    const int n0   = blockIdx.x * 64;
    const int t    = threadIdx.x;
    const int w    = t >> 5;
    const int lane = t & 31;
    const int gid  = lane >> 2;   // 0..7
    const int tig  = lane & 3;    // 0..3
    const int wr   = w >> 1;      // 0..3
    const int wcl  = w & 1;       // 0..1

    // load Q tile (64 x 256), already tf32-rounded
    for (int i = t; i < 64*64; i += 256) {
        int r = i >> 6, c4 = i & 63;
        *(float4*)(Qs + r*SQ + c4*4) =
            *(const float4*)(g_q + (b*NN + n0 + r)*NC + c4*4);
    }
    if (t < 64) { m_row[t] = -INFINITY; l_row[t] = 0.f; }

    float o[2][8][4];  // [mt][nt][reg] : O^T accum, rows 32w+16mt+{gid,gid+8}, cols 8nt+2tig+{0,1}
    #pragma unroll
    for (int mt = 0; mt < 2; mt++)
        #pragma unroll
        for (int nt = 0; nt < 8; nt++)
            #pragma unroll
            for (int r = 0; r < 4; r++) o[mt][nt][r] = 0.f;

    const int r0 = 16*wr + gid;   // S-tile row for this thread

    for (int kt = 0; kt < 64; kt++) {
        const int k0g = kt * 64;
        for (int i = t; i < 64*64; i += 256) {
            int r = i >> 6, c4 = i & 63;
            *(float4*)(Ks + r*SQ + c4*4) =
                *(const float4*)(g_k + (b*NN + k0g + r)*NC + c4*4);
            *(float4*)(Vs + r*SV + c4*4) =
                *(const float4*)(g_v + (b*NN + k0g + r)*NC + c4*4);
        }
        __syncthreads();

        // --- S = Q K^T : warp tile 16x32 ---
        float sacc[4][4];
        #pragma unroll
        for (int j = 0; j < 4; j++)
            #pragma unroll
            for (int r = 0; r < 4; r++) sacc[j][r] = 0.f;

        const float* qb = Qs + r0*SQ;
        const float* kb = Ks + (32*wcl + gid)*SQ;
        #pragma unroll 4
        for (int k0 = 0; k0 < 256; k0 += 8) {
            unsigned a[4];
            a[0] = fbits(qb[k0 + tig]);
            a[1] = fbits(qb[8*SQ + k0 + tig]);
            a[2] = fbits(qb[k0 + tig + 4]);
            a[3] = fbits(qb[8*SQ + k0 + tig + 4]);
            #pragma unroll
            for (int j = 0; j < 4; j++) {
                unsigned b0 = fbits(kb[j*8*SQ + k0 + tig]);
                unsigned b1 = fbits(kb[j*8*SQ + k0 + tig + 4]);
                mma_tf32(sacc[j], a, b0, b1);
            }
        }
        #pragma unroll
        for (int j = 0; j < 4; j++) {
            int c = 32*wcl + 8*j + 2*tig;
            Ss[r0*SSTR + c]       = sacc[j][0];
            Ss[r0*SSTR + c + 1]   = sacc[j][1];
            Ss[(r0+8)*SSTR + c]   = sacc[j][2];
            Ss[(r0+8)*SSTR + c+1] = sacc[j][3];
        }
        __syncthreads();

        // --- online softmax: 4 lanes per row; P stored tf32-rounded ---
        {
            const int r = t >> 2, q = t & 3;
            float* srow = Ss + r*SSTR + q*16;
            float mx = -INFINITY;
            #pragma unroll
            for (int k = 0; k < 16; k++) mx = fmaxf(mx, srow[k]);
            mx = fmaxf(mx, __shfl_xor_sync(0xffffffffu, mx, 1));
            mx = fmaxf(mx, __shfl_xor_sync(0xffffffffu, mx, 2));
            const float m_old = m_row[r];
            const float m_new = fmaxf(m_old, mx);
            float ps = 0.f;
            #pragma unroll
            for (int k = 0; k < 16; k++) {
                float p = __expf(srow[k] - m_new);
                srow[k] = __uint_as_float(tf32r(p));
                ps += p;
            }
            ps += __shfl_xor_sync(0xffffffffu, ps, 1);
            ps += __shfl_xor_sync(0xffffffffu, ps, 2);
            if (q == 0) {
                float corr = __expf(m_old - m_new);
                s_scal[r] = corr;
                l_row[r]  = l_row[r]*corr + ps;
                m_row[r]  = m_new;
            }
        }
        __syncthreads();

        // --- O^T = O^T*corr + V^T P^T ---
        #pragma unroll
        for (int nt = 0; nt < 8; nt++) {
            float s0 = s_scal[8*nt + 2*tig];
            float s1 = s_scal[8*nt + 2*tig + 1];
            #pragma unroll
            for (int mt = 0; mt < 2; mt++) {
                o[mt][nt][0] *= s0; o[mt][nt][1] *= s1;
                o[mt][nt][2] *= s0; o[mt][nt][3] *= s1;
            }
        }
        #pragma unroll 2
        for (int k0 = 0; k0 < 64; k0 += 8) {
            unsigned av[2][4];
            #pragma unroll
            for (int mt = 0; mt < 2; mt++) {
                int m = 32*w + 16*mt + gid;
                av[mt][0] = fbits(Vs[(k0 + tig)*SV + m]);
                av[mt][1] = fbits(Vs[(k0 + tig)*SV + m + 8]);
                av[mt][2] = fbits(Vs[(k0 + tig + 4)*SV + m]);
                av[mt][3] = fbits(Vs[(k0 + tig + 4)*SV + m + 8]);
            }
            #pragma unroll
            for (int nt = 0; nt < 8; nt++) {
                int qn = 8*nt + gid;
                unsigned b0 = fbits(Ss[qn*SSTR + k0 + tig]);
                unsigned b1 = fbits(Ss[qn*SSTR + k0 + tig + 4]);
                mma_tf32(o[0][nt], av[0], b0, b1);
                mma_tf32(o[1][nt], av[1], b0, b1);
            }
        }
        __syncthreads();
    }

    // --- write O^T/l to Ot smem (already channel-major; no transpose needed) ---
    float* Ot = Qs;  // 256 x SSTR = 17408 floats, fits in Qs+Ks region
    #pragma unroll
    for (int nt = 0; nt < 8; nt++) {
        int q = 8*nt + 2*tig;
        float li0 = __fdividef(1.f, l_row[q]);
        float li1 = __fdividef(1.f, l_row[q + 1]);
        #pragma unroll
        for (int mt = 0; mt < 2; mt++) {
            int c = 32*w + 16*mt + gid;
            Ot[c*SSTR + q]         = o[mt][nt][0] * li0;
            Ot[c*SSTR + q + 1]     = o[mt][nt][1] * li1;
            Ot[(c+8)*SSTR + q]     = o[mt][nt][2] * li0;
            Ot[(c+8)*SSTR + q + 1] = o[mt][nt][3] * li1;
        }
    }
    __syncthreads();

    const float g = gamma[0];
    #pragma unroll
    for (int pass = 0; pass < 4; pass++) {
        int c = pass*64 + (t >> 2);
        #pragma unroll
        for (int j = 0; j < 4; j++) {
            int f4 = (t & 3) + j*4;
            float4 ov = *(float4*)(Ot + c*SSTR + f4*4);
            float4 xv = *(const float4*)(x + (b*NC + c)*NN + n0 + f4*4);
            float4 r;
            r.x = g*ov.x + xv.x; r.y = g*ov.y + xv.y;
            r.z = g*ov.z + xv.z; r.w = g*ov.w + xv.w;
            *(float4*)(out + (b*NC + c)*NN + n0 + f4*4) = r;
        }
    }
}

// ---------------------------------------------------------------------------

extern "C" void kernel_launch(void* const* d_in, const int* in_sizes, int n_in,
                              void* d_out, int out_size)
{
    const float* x     = (const float*)d_in[0];
    const float* Wq    = (const float*)d_in[1];
    const float* Wk    = (const float*)d_in[2];
    const float* Wv    = (const float*)d_in[3];
    const float* gamma = (const float*)d_in[4];
    float* out = (float*)d_out;

    const int smem_bytes = (2*64*SQ + 64*SV + 64*SSTR + 3*64) * (int)sizeof(float); // 218880
    cudaFuncSetAttribute(flash_kernel,
                         cudaFuncAttributeMaxDynamicSharedMemorySize, smem_bytes);

    dim3 gp(NN/64, NC/64, 3*NB);
    qkv_proj_kernel<<<gp, 256>>>(x, Wq, Wk, Wv);

    dim3 gf(NN/64, NB);
    flash_kernel<<<gf, 256, smem_bytes>>>(x, gamma, out);
}